// round 3
// baseline (speedup 1.0000x reference)
#include <cuda_runtime.h>

#define EPSBN 1e-5f
#define HH 300
#define WW 300
#define HW (HH * WW)
#define BB 4
#define HCH 64
#define CBLK 8
#define TX 64
#define TY 16

typedef unsigned long long ull;

// Scratch activations (device globals — allocation-guard-safe)
__device__ float g_trunk[(size_t)BB * HCH * HW];
__device__ float g_mid_hm[(size_t)BB * HCH * HW];
__device__ float g_mid_rg[(size_t)BB * HCH * HW];

__device__ __forceinline__ void ffma2(ull& d, ull a, ull b) {
    asm("fma.rn.f32x2 %0, %1, %2, %0;" : "+l"(d) : "l"(a), "l"(b));
}
__device__ __forceinline__ ull packf2(float lo, float hi) {
    ull r;
    asm("mov.b64 %0, {%1, %2};" : "=l"(r) : "f"(lo), "f"(hi));
    return r;
}
__device__ __forceinline__ void unpackf2(ull v, float& lo, float& hi) {
    asm("mov.b64 {%0, %1}, %2;" : "=f"(lo), "=f"(hi) : "l"(v));
}

// ---------------------------------------------------------------------------
// conv3x3 + BN + ReLU via packed FFMA2.
// Block: 256 threads, tile 64x16 pixels x 16 oc (group = blockIdx.z & 3).
// Thread: 1x4 pixels x 16 oc, accumulated as 32 packed f32x2 registers.
// ---------------------------------------------------------------------------
template <int CIN>
__global__ __launch_bounds__(256, 2) void conv3x3_kernel(
    const float* __restrict__ in, const float* __restrict__ wgt,
    const float* __restrict__ gg, const float* __restrict__ bbp,
    const float* __restrict__ mm, const float* __restrict__ vv,
    float* __restrict__ out)
{
    __shared__ float s_in[CBLK][18 * 67];     // halo tile, pitch 67
    __shared__ float s_w[CBLK][9 * 32];       // [k][oc] duplicated {w,w} pairs

    const int tid = threadIdx.x;
    const int tx = tid & 15, ty = tid >> 4;
    const int bx = blockIdx.x * TX, by = blockIdx.y * TY;
    const int b = blockIdx.z >> 2;
    const int oc0 = (blockIdx.z & 3) * 16;

    ull accA[16], accB[16];                   // accA: px{0,1}, accB: px{2,3}
#pragma unroll
    for (int i = 0; i < 16; i++) { accA[i] = 0ull; accB[i] = 0ull; }

    const float* inb = in + (size_t)b * CIN * HW;

    for (int cc = 0; cc < CIN; cc += CBLK) {
        __syncthreads();
        // stage input halo (CBLK channels, 18x66)
        for (int i = tid; i < CBLK * 18 * 66; i += 256) {
            int c = i / 1188, rem = i % 1188;
            int r = rem / 66, col = rem % 66;
            int gy = by - 1 + r, gx = bx - 1 + col;
            float v = 0.f;
            if ((unsigned)gy < HH && (unsigned)gx < WW)
                v = inb[(size_t)(cc + c) * HW + gy * WW + gx];
            s_in[c][r * 67 + col] = v;
        }
        // stage weights duplicated: s_w[c][(k*16+ocl)*2 .. +1] = w
        for (int i = tid; i < CBLK * 144; i += 256) {
            int c = i / 144, j = i % 144;
            int ocl = j / 9, k = j % 9;
            float w = wgt[((size_t)(oc0 + ocl) * CIN + cc + c) * 9 + k];
            s_w[c][(k * 16 + ocl) * 2 + 0] = w;
            s_w[c][(k * 16 + ocl) * 2 + 1] = w;
        }
        __syncthreads();

#pragma unroll 1
        for (int c = 0; c < CBLK; c++) {
            // packed pixel pairs: P[r][i] = (p[i], p[i+1]), i = 0..4
            ull P[3][5];
#pragma unroll
            for (int r = 0; r < 3; r++) {
                float t[6];
#pragma unroll
                for (int q = 0; q < 6; q++)
                    t[q] = s_in[c][(ty + r) * 67 + 4 * tx + q];
#pragma unroll
                for (int i = 0; i < 5; i++)
                    P[r][i] = packf2(t[i], t[i + 1]);
            }
#pragma unroll
            for (int dy = 0; dy < 3; dy++)
#pragma unroll
                for (int dx = 0; dx < 3; dx++) {
                    const ull pA = P[dy][dx];        // px0,px1
                    const ull pB = P[dy][dx + 2];    // px2,px3
                    const ulonglong2* wrow =
                        (const ulonglong2*)&s_w[c][(dy * 3 + dx) * 32];
#pragma unroll
                    for (int g = 0; g < 8; g++) {
                        ulonglong2 w = wrow[g];      // 2 oc, each {w,w}
                        ffma2(accA[2 * g + 0], w.x, pA);
                        ffma2(accB[2 * g + 0], w.x, pB);
                        ffma2(accA[2 * g + 1], w.y, pA);
                        ffma2(accB[2 * g + 1], w.y, pB);
                    }
                }
        }
    }

    const int gy = by + ty, gx0 = bx + 4 * tx;
    if (gy < HH && gx0 < WW) {   // gx0, WW multiples of 4 -> full float4 in bounds
#pragma unroll
        for (int j = 0; j < 16; j++) {
            int oc = oc0 + j;
            float sc = __ldg(&gg[oc]) * rsqrtf(__ldg(&vv[oc]) + EPSBN);
            float sh = __ldg(&bbp[oc]) - __ldg(&mm[oc]) * sc;
            float4 o;
            unpackf2(accA[j], o.x, o.y);
            unpackf2(accB[j], o.z, o.w);
            o.x = fmaxf(o.x * sc + sh, 0.f);
            o.y = fmaxf(o.y * sc + sh, 0.f);
            o.z = fmaxf(o.z * sc + sh, 0.f);
            o.w = fmaxf(o.w * sc + sh, 0.f);
            *(float4*)&out[(size_t)(b * HCH + oc) * HW + gy * WW + gx0] = o;
        }
    }
}

// ---------------------------------------------------------------------------
// Fused 1x1 convs for both heads: reads both mid activations, writes d_out.
// ---------------------------------------------------------------------------
__global__ __launch_bounds__(256) void head1x1_kernel(
    const float* __restrict__ w_hm2, const float* __restrict__ b_hm2,
    const float* __restrict__ w_rg2, const float* __restrict__ b_rg2,
    float* __restrict__ out)
{
    __shared__ float s_wh[3 * 64];
    __shared__ float s_wr[8 * 64];
    const int tid = threadIdx.x;
    for (int i = tid; i < 192; i += 256) s_wh[i] = w_hm2[i];
    for (int i = tid; i < 512; i += 256) s_wr[i] = w_rg2[i];
    __syncthreads();

    size_t idx = (size_t)blockIdx.x * 256 + tid;
    if (idx >= (size_t)BB * HW) return;
    int b = (int)(idx / HW);
    int p = (int)(idx % HW);

    const float* mh = g_mid_hm + (size_t)b * HCH * HW + p;
    const float* mr = g_mid_rg + (size_t)b * HCH * HW + p;

    float sh0 = b_hm2[0], sh1 = b_hm2[1], sh2 = b_hm2[2];
    float sr[8];
#pragma unroll
    for (int j = 0; j < 8; j++) sr[j] = b_rg2[j];

#pragma unroll 4
    for (int c = 0; c < 64; c++) {
        float a = mh[(size_t)c * HW];
        sh0 += a * s_wh[0 * 64 + c];
        sh1 += a * s_wh[1 * 64 + c];
        sh2 += a * s_wh[2 * 64 + c];
        float r = mr[(size_t)c * HW];
#pragma unroll
        for (int j = 0; j < 8; j++) sr[j] += r * s_wr[j * 64 + c];
    }

    float* hm = out;
    float* rg = out + (size_t)BB * 3 * HW;
    hm[((size_t)b * 3 + 0) * HW + p] = sh0;
    hm[((size_t)b * 3 + 1) * HW + p] = sh1;
    hm[((size_t)b * 3 + 2) * HW + p] = sh2;
#pragma unroll
    for (int j = 0; j < 8; j++)
        rg[((size_t)b * 8 + j) * HW + p] = sr[j];
}

// ---------------------------------------------------------------------------
extern "C" void kernel_launch(void* const* d_in, const int* in_sizes, int n_in,
                              void* d_out, int out_size)
{
    const float* bev    = (const float*)d_in[0];
    const float* w_sh   = (const float*)d_in[1];
    const float* g_sh   = (const float*)d_in[2];
    const float* b_sh   = (const float*)d_in[3];
    const float* m_sh   = (const float*)d_in[4];
    const float* v_sh   = (const float*)d_in[5];
    const float* w_hm1  = (const float*)d_in[6];
    const float* g_hm1  = (const float*)d_in[7];
    const float* b_hm1  = (const float*)d_in[8];
    const float* m_hm1  = (const float*)d_in[9];
    const float* v_hm1  = (const float*)d_in[10];
    const float* w_hm2  = (const float*)d_in[11];
    const float* b_hm2  = (const float*)d_in[12];
    const float* w_rg1  = (const float*)d_in[13];
    const float* g_rg1  = (const float*)d_in[14];
    const float* b_rg1  = (const float*)d_in[15];
    const float* m_rg1  = (const float*)d_in[16];
    const float* v_rg1  = (const float*)d_in[17];
    const float* w_rg2  = (const float*)d_in[18];
    const float* b_rg2  = (const float*)d_in[19];

    float *trunk, *midh, *midr;
    cudaGetSymbolAddress((void**)&trunk, g_trunk);
    cudaGetSymbolAddress((void**)&midh, g_mid_hm);
    cudaGetSymbolAddress((void**)&midr, g_mid_rg);

    dim3 grid((WW + TX - 1) / TX, (HH + TY - 1) / TY, BB * 4);   // 5 x 19 x 16

    conv3x3_kernel<256><<<grid, 256>>>(bev, w_sh, g_sh, b_sh, m_sh, v_sh, trunk);
    conv3x3_kernel<64><<<grid, 256>>>(trunk, w_hm1, g_hm1, b_hm1, m_hm1, v_hm1, midh);
    conv3x3_kernel<64><<<grid, 256>>>(trunk, w_rg1, g_rg1, b_rg1, m_rg1, v_rg1, midr);

    int npix = BB * HW;
    head1x1_kernel<<<(npix + 255) / 256, 256>>>(w_hm2, b_hm2, w_rg2, b_rg2, (float*)d_out);
}

// round 5
// speedup vs baseline: 4.1095x; 4.1095x over previous
#include <cuda_runtime.h>
#include <cuda_bf16.h>
#include <cstdint>

#define EPSBN 1e-5f
#define HH 300
#define WW 300
#define HW 90000
#define BB 4

// ===========================================================================
// PTX helpers — baseline (non-arch-accelerated) instructions only
// ===========================================================================
__device__ __forceinline__ uint32_t smem_u32(const void* p) {
    uint32_t a;
    asm("{ .reg .u64 t; cvta.to.shared.u64 t, %1; cvt.u32.u64 %0, t; }"
        : "=r"(a) : "l"(p));
    return a;
}
__device__ __forceinline__ void ldsm4(uint32_t* r, uint32_t addr) {
    asm volatile("ldmatrix.sync.aligned.m8n8.x4.shared.b16 {%0,%1,%2,%3}, [%4];"
                 : "=r"(r[0]), "=r"(r[1]), "=r"(r[2]), "=r"(r[3]) : "r"(addr));
}
__device__ __forceinline__ void mma_bf16(float* c, const uint32_t* a,
                                         uint32_t b0, uint32_t b1) {
    asm volatile(
        "mma.sync.aligned.m16n8k16.row.col.f32.bf16.bf16.f32 "
        "{%0,%1,%2,%3}, {%4,%5,%6,%7}, {%8,%9}, {%0,%1,%2,%3};"
        : "+f"(c[0]), "+f"(c[1]), "+f"(c[2]), "+f"(c[3])
        : "r"(a[0]), "r"(a[1]), "r"(a[2]), "r"(a[3]), "r"(b0), "r"(b1));
}
#define CP_ASYNC16(dst, src) \
    asm volatile("cp.async.cg.shared.global [%0], [%1], 16;" :: "r"(dst), "l"(src))
#define CP_COMMIT() asm volatile("cp.async.commit_group;" ::: "memory")
#define CP_WAIT1()  asm volatile("cp.async.wait_group 1;" ::: "memory")
#define CP_WAIT0()  asm volatile("cp.async.wait_group 0;" ::: "memory")

// ===========================================================================
// Device scratch (allocation-guard-safe)
// ===========================================================================
__device__ __nv_bfloat16 g_bev_hi[(size_t)BB * HW * 256];
__device__ __nv_bfloat16 g_bev_lo[(size_t)BB * HW * 256];
__device__ __nv_bfloat16 g_tr_hi[(size_t)BB * HW * 64];
__device__ __nv_bfloat16 g_tr_lo[(size_t)BB * HW * 64];
__device__ __nv_bfloat16 g_wimg_sh[36 * 9216];  // trunk: 4 cch x 9 shifts, [hi 64x72 | lo 64x72]
__device__ __nv_bfloat16 g_wimg_hm[9 * 9216];
__device__ __nv_bfloat16 g_wimg_rg[9 * 9216];

// ===========================================================================
// NCHW fp32 -> NHWC bf16 hi/lo (bev)
// ===========================================================================
__global__ __launch_bounds__(256) void nhwc_kernel(const float* __restrict__ in)
{
    __shared__ float tile[32][33];
    const int tx = threadIdx.x & 31, ty = threadIdx.x >> 5;
    const int w0 = blockIdx.x * 32, c0 = blockIdx.y * 32;
    const int b = blockIdx.z / HH, h = blockIdx.z % HH;
#pragma unroll
    for (int q = 0; q < 4; q++) {
        int c = c0 + ty * 4 + q, w = w0 + tx;
        tile[ty * 4 + q][tx] = (w < WW) ? in[(((size_t)b * 256 + c) * HH + h) * WW + w] : 0.f;
    }
    __syncthreads();
#pragma unroll
    for (int q = 0; q < 4; q++) {
        int w = w0 + ty * 4 + q;
        if (w >= WW) continue;
        float x = tile[tx][ty * 4 + q];
        __nv_bfloat16 hi = __float2bfloat16(x);
        __nv_bfloat16 lo = __float2bfloat16(x - __bfloat162float(hi));
        size_t o = ((size_t)b * HW + (size_t)h * WW + w) * 256 + c0 + tx;
        g_bev_hi[o] = hi;
        g_bev_lo[o] = lo;
    }
}

// ===========================================================================
// Weight prep: w[oc][ci][3][3] fp32 -> per (cchunk, shift) [64 oc][72] hi|lo
// ===========================================================================
__global__ void prep_w_kernel(const float* __restrict__ w,
                              __nv_bfloat16* __restrict__ dst, int CIN)
{
    int i = blockIdx.x * 256 + threadIdx.x;
    if (i >= 64 * CIN * 9) return;
    int kk = i % 9;
    int ci = (i / 9) % CIN;
    int oc = i / (9 * CIN);
    float x = w[i];
    __nv_bfloat16 hi = __float2bfloat16(x);
    __nv_bfloat16 lo = __float2bfloat16(x - __bfloat162float(hi));
    int cc = ci >> 6, c = ci & 63;
    size_t base = (size_t)(cc * 9 + kk) * 9216;
    dst[base + oc * 72 + c] = hi;
    dst[base + 4608 + oc * 72 + c] = lo;
}

// ===========================================================================
// conv3x3 + BN + ReLU via mma.sync bf16, 3-pass hi/lo split.
// CTA: 256 thr (8 warps). Tile: 8 rows x 16 cols x 64 oc. Warp w = row by+w,
// M = 16 x-pixels, N = 64 oc, K = 64ch per cchunk per shift.
// NOUT==0: trunk -> NHWC hi/lo.  NOUT>0: fused 1x1+bias -> NCHW fp32.
// ===========================================================================
template <int CCH, int NOUT>
__global__ __launch_bounds__(256, 2) void conv_mma_kernel(
    const __nv_bfloat16* __restrict__ act_hi, const __nv_bfloat16* __restrict__ act_lo,
    const __nv_bfloat16* __restrict__ wimg,
    const float* __restrict__ gg, const float* __restrict__ bbp,
    const float* __restrict__ mm, const float* __restrict__ vv,
    const float* __restrict__ w2, const float* __restrict__ b2,
    __nv_bfloat16* __restrict__ out_hi, __nv_bfloat16* __restrict__ out_lo,
    float* __restrict__ outf)
{
    constexpr int CIN = CCH * 64;
    constexpr int NSH = CCH * 9;

    extern __shared__ __align__(16) unsigned char dynsmem[];
    __nv_bfloat16* sB = (__nv_bfloat16*)dynsmem;              // 2 x 9216 elems (36864 B)
    __nv_bfloat16* s_hh = (__nv_bfloat16*)(dynsmem + 36864);  // 180*72
    __nv_bfloat16* s_hl = s_hh + 180 * 72;
    float* s_mid = (float*)(dynsmem + 36864);                 // alias (heads, post-mma)

    __shared__ float s_scale[64], s_shift[64];
    __shared__ float s_w2[(NOUT > 0 ? NOUT : 1) * 64];
    __shared__ float s_b2[(NOUT > 0 ? NOUT : 1)];

    const int tid = threadIdx.x;
    const int w = tid >> 5, lane = tid & 31;
    const int bx = blockIdx.x * 16, by = blockIdx.y * 8;
    const int b = blockIdx.z;

    if (tid < 64) {
        float sc = gg[tid] * rsqrtf(vv[tid] + EPSBN);
        s_scale[tid] = sc;
        s_shift[tid] = bbp[tid] - mm[tid] * sc;
    }
    if (NOUT > 0) {
        for (int i = tid; i < NOUT * 64; i += 256) s_w2[i] = w2[i];
        if (tid < NOUT) s_b2[tid] = b2[tid];
    }

    // lane invariants
    const int mA = lane & 15;
    const int kselA = (lane >> 4) * 8;                      // elems
    const int oclB = (lane & 7) + ((lane >> 4) & 1) * 8;
    const int koffB = (lane & 8) ? 8 : 0;                   // elems

    const uint32_t sB_u = smem_u32(sB);
    const uint32_t shh_u = smem_u32(s_hh);

    float acc[8][4];
#pragma unroll
    for (int i = 0; i < 8; i++)
#pragma unroll
        for (int j = 0; j < 4; j++) acc[i][j] = 0.f;

    // prefetch first B image (hi+lo, 18432 B)
    {
        const char* src = (const char*)wimg;
        for (int i = tid; i < 1152; i += 256)
            CP_ASYNC16(sB_u + i * 16, src + i * 16);
        CP_COMMIT();
    }

    for (int cc = 0; cc < CCH; cc++) {
        __syncthreads();   // halo reuse safe
        // stage halo: 180 px x 64ch hi+lo, pixel pitch 72 elems
        for (int idx = tid; idx < 180 * 8; idx += 256) {
            int pix = idx >> 3, j = idx & 7;
            int r = pix / 18, col = pix % 18;
            int gy = by - 1 + r, gx = bx - 1 + col;
            uint4 vh = make_uint4(0, 0, 0, 0), vl = make_uint4(0, 0, 0, 0);
            if ((unsigned)gy < HH && (unsigned)gx < WW) {
                size_t e = ((size_t)b * HW + (size_t)gy * WW + gx) * CIN + cc * 64;
                vh = ((const uint4*)(act_hi + e))[j];
                vl = ((const uint4*)(act_lo + e))[j];
            }
            ((uint4*)(s_hh + pix * 72))[j] = vh;
            ((uint4*)(s_hl + pix * 72))[j] = vl;
        }

#pragma unroll 1
        for (int k = 0; k < 9; k++) {
            const int s = cc * 9 + k;
            const uint32_t cur = (uint32_t)(s & 1);
            if (s + 1 < NSH) {
                const char* src = (const char*)(wimg + (size_t)(s + 1) * 9216);
                uint32_t dst = sB_u + (uint32_t)((s + 1) & 1) * 18432;
                for (int i = tid; i < 1152; i += 256)
                    CP_ASYNC16(dst + i * 16, src + i * 16);
                CP_COMMIT();
                CP_WAIT1();
            } else {
                CP_WAIT0();
            }
            __syncthreads();

            const int ky = k / 3, kx = k - 3 * ky;
            const uint32_t aH = shh_u + (uint32_t)((((w + ky) * 18 + mA + kx) * 72 + kselA) * 2);
            const uint32_t aL = aH + 180 * 72 * 2;
            const uint32_t bH = sB_u + cur * 18432 + (uint32_t)((oclB * 72 + koffB) * 2);
            const uint32_t bL = bH + 9216;

#pragma unroll
            for (int kc = 0; kc < 4; kc++) {
                uint32_t ah[4], al[4];
                ldsm4(ah, aH + kc * 32);
                ldsm4(al, aL + kc * 32);
#pragma unroll
                for (int ng = 0; ng < 4; ng++) {
                    uint32_t bh[4], bl[4];
                    ldsm4(bh, bH + ng * 2304 + kc * 32);
                    ldsm4(bl, bL + ng * 2304 + kc * 32);
                    mma_bf16(acc[2 * ng + 0], ah, bh[0], bh[1]);
                    mma_bf16(acc[2 * ng + 1], ah, bh[2], bh[3]);
                    mma_bf16(acc[2 * ng + 0], ah, bl[0], bl[1]);
                    mma_bf16(acc[2 * ng + 1], ah, bl[2], bl[3]);
                    mma_bf16(acc[2 * ng + 0], al, bh[0], bh[1]);
                    mma_bf16(acc[2 * ng + 1], al, bh[2], bh[3]);
                }
            }
            __syncthreads();   // protect sB[cur] + halo from next iteration
        }
    }

    // ---- epilogue: BN + ReLU ----
    // acc[nt][cj]: oc = nt*8 + (lane&3)*2 + (cj&1); m = (lane>>2) + (cj>>1)*8
#pragma unroll
    for (int nt = 0; nt < 8; nt++)
#pragma unroll
        for (int cj = 0; cj < 4; cj++) {
            int oc = nt * 8 + (lane & 3) * 2 + (cj & 1);
            acc[nt][cj] = fmaxf(acc[nt][cj] * s_scale[oc] + s_shift[oc], 0.f);
        }

    const int y = by + w;

    if (NOUT == 0) {
        // trunk: write NHWC hi/lo bf16 pairs
#pragma unroll
        for (int side = 0; side < 2; side++) {
            int m = (lane >> 2) + side * 8;
            int x = bx + m;
            if (y < HH && x < WW) {
                size_t base = ((size_t)b * HW + (size_t)y * WW + x) * 64;
#pragma unroll
                for (int nt = 0; nt < 8; nt++) {
                    int oc0 = nt * 8 + (lane & 3) * 2;
                    float v0 = acc[nt][side * 2 + 0];
                    float v1 = acc[nt][side * 2 + 1];
                    __nv_bfloat16 h0 = __float2bfloat16(v0);
                    __nv_bfloat16 h1 = __float2bfloat16(v1);
                    __nv_bfloat162 hp; hp.x = h0; hp.y = h1;
                    __nv_bfloat162 lp;
                    lp.x = __float2bfloat16(v0 - __bfloat162float(h0));
                    lp.y = __float2bfloat16(v1 - __bfloat162float(h1));
                    *(__nv_bfloat162*)(out_hi + base + oc0) = hp;
                    *(__nv_bfloat162*)(out_lo + base + oc0) = lp;
                }
            }
        }
    } else {
        // heads: stage mid into smem, then 1x1 conv + bias -> NCHW fp32
#pragma unroll
        for (int side = 0; side < 2; side++) {
            int m = (lane >> 2) + side * 8;
            int p = w * 16 + m;
#pragma unroll
            for (int nt = 0; nt < 8; nt++) {
                int oc0 = nt * 8 + (lane & 3) * 2;
                s_mid[p * 65 + oc0] = acc[nt][side * 2 + 0];
                s_mid[p * 65 + oc0 + 1] = acc[nt][side * 2 + 1];
            }
        }
        __syncthreads();
        if (tid < 128) {
            int p = tid;
            int yy = by + (p >> 4), xx = bx + (p & 15);
            if (yy < HH && xx < WW) {
                const float* row = s_mid + p * 65;
                float o[NOUT > 0 ? NOUT : 1];
#pragma unroll
                for (int n = 0; n < NOUT; n++) o[n] = s_b2[n];
#pragma unroll 8
                for (int c = 0; c < 64; c++) {
                    float a = row[c];
#pragma unroll
                    for (int n = 0; n < NOUT; n++) o[n] += a * s_w2[n * 64 + c];
                }
#pragma unroll
                for (int n = 0; n < NOUT; n++)
                    outf[((size_t)(b * NOUT + n) * HH + yy) * WW + xx] = o[n];
            }
        }
    }
}

// ===========================================================================
extern "C" void kernel_launch(void* const* d_in, const int* in_sizes, int n_in,
                              void* d_out, int out_size)
{
    const float* bev   = (const float*)d_in[0];
    const float* w_sh  = (const float*)d_in[1];
    const float* g_sh  = (const float*)d_in[2];
    const float* b_sh  = (const float*)d_in[3];
    const float* m_sh  = (const float*)d_in[4];
    const float* v_sh  = (const float*)d_in[5];
    const float* w_hm1 = (const float*)d_in[6];
    const float* g_hm1 = (const float*)d_in[7];
    const float* b_hm1 = (const float*)d_in[8];
    const float* m_hm1 = (const float*)d_in[9];
    const float* v_hm1 = (const float*)d_in[10];
    const float* w_hm2 = (const float*)d_in[11];
    const float* b_hm2 = (const float*)d_in[12];
    const float* w_rg1 = (const float*)d_in[13];
    const float* g_rg1 = (const float*)d_in[14];
    const float* b_rg1 = (const float*)d_in[15];
    const float* m_rg1 = (const float*)d_in[16];
    const float* v_rg1 = (const float*)d_in[17];
    const float* w_rg2 = (const float*)d_in[18];
    const float* b_rg2 = (const float*)d_in[19];

    __nv_bfloat16 *bev_hi, *bev_lo, *tr_hi, *tr_lo, *wi_sh, *wi_hm, *wi_rg;
    cudaGetSymbolAddress((void**)&bev_hi, g_bev_hi);
    cudaGetSymbolAddress((void**)&bev_lo, g_bev_lo);
    cudaGetSymbolAddress((void**)&tr_hi, g_tr_hi);
    cudaGetSymbolAddress((void**)&tr_lo, g_tr_lo);
    cudaGetSymbolAddress((void**)&wi_sh, g_wimg_sh);
    cudaGetSymbolAddress((void**)&wi_hm, g_wimg_hm);
    cudaGetSymbolAddress((void**)&wi_rg, g_wimg_rg);

    const int DSMEM = 36864 + 180 * 72 * 2 * 2;   // 88704 B
    cudaFuncSetAttribute(conv_mma_kernel<4, 0>, cudaFuncAttributeMaxDynamicSharedMemorySize, DSMEM);
    cudaFuncSetAttribute(conv_mma_kernel<1, 3>, cudaFuncAttributeMaxDynamicSharedMemorySize, DSMEM);
    cudaFuncSetAttribute(conv_mma_kernel<1, 8>, cudaFuncAttributeMaxDynamicSharedMemorySize, DSMEM);

    // 1. bev NCHW fp32 -> NHWC bf16 hi/lo
    nhwc_kernel<<<dim3(10, 8, BB * HH), 256>>>(bev);

    // 2. weight images
    prep_w_kernel<<<(64 * 256 * 9 + 255) / 256, 256>>>(w_sh, wi_sh, 256);
    prep_w_kernel<<<(64 * 64 * 9 + 255) / 256, 256>>>(w_hm1, wi_hm, 64);
    prep_w_kernel<<<(64 * 64 * 9 + 255) / 256, 256>>>(w_rg1, wi_rg, 64);

    dim3 grid(19, 38, BB);   // 16x8 pixel tiles

    // 3. trunk conv -> NHWC hi/lo
    conv_mma_kernel<4, 0><<<grid, 256, DSMEM>>>(
        bev_hi, bev_lo, wi_sh, g_sh, b_sh, m_sh, v_sh,
        nullptr, nullptr, tr_hi, tr_lo, nullptr);

    // 4. heads (fused 1x1 epilogue -> d_out)
    float* out = (float*)d_out;
    conv_mma_kernel<1, 3><<<grid, 256, DSMEM>>>(
        tr_hi, tr_lo, wi_hm, g_hm1, b_hm1, m_hm1, v_hm1,
        w_hm2, b_hm2, nullptr, nullptr, out);
    conv_mma_kernel<1, 8><<<grid, 256, DSMEM>>>(
        tr_hi, tr_lo, wi_rg, g_rg1, b_rg1, m_rg1, v_rg1,
        w_rg2, b_rg2, nullptr, nullptr, out + (size_t)BB * 3 * HW);
}